// round 4
// baseline (speedup 1.0000x reference)
#include <cuda_runtime.h>
#include <math.h>

// ---------------- problem constants ----------------
#define Bb   4
#define Qq   8192
#define Ee   256
#define Hh   8
#define Ll   4
#define Pp   4
#define HDd  32
#define VLENv 21760   // 128*128 + 64*64 + 32*32 + 16*16

// ---------------- scratch (device globals; no allocation allowed) ----------------
__device__ float g_v   [(size_t)Bb * VLENv * Ee];   // value @ V_W^T        (~89 MB)
__device__ float g_off [(size_t)Bb * Qq   * Ee];    // tanh offsets         (~34 MB)
__device__ float g_attn[(size_t)Bb * Qq   * 128];   // attention logits     (~17 MB)
__device__ float g_samp[(size_t)Bb * Qq   * Ee];    // sampled output       (~34 MB)

// ---------------------------------------------------------------------------
// Generic SGEMM:  C[M,N] = act( A[M,K] @ W[N,K]^T + bias )
// A row-major [M,K], W row-major [N,K] (i.e. both are "rows of K"), so both
// tiles are transpose-loaded into smem symmetrically.
// Tile: BM=BN=128, BK=8, 256 threads, 8x8 outputs/thread, register prefetch.
// Requires: M%128==0, N%128==0, K%8==0, pointers 16B aligned. (All true here.)
// ---------------------------------------------------------------------------
template<int ACT, int WITH_BIAS>
__global__ void __launch_bounds__(256) sgemm_tn(
    const float* __restrict__ A,
    const float* __restrict__ W,
    const float* __restrict__ bias,
    float* __restrict__ C,
    int M, int N, int K)
{
    constexpr int BM = 128, BN = 128, BK = 8;
    __shared__ __align__(16) float As[BK][BM + 4];
    __shared__ __align__(16) float Ws[BK][BN + 4];

    const int tid = threadIdx.x;
    const int bm  = blockIdx.y * BM;
    const int bn  = blockIdx.x * BN;

    // global->smem load mapping: each thread loads one float4 from A and one from W
    const int lrow = tid >> 1;          // 0..127
    const int kq   = (tid & 1) * 4;     // 0 or 4

    const float* Ap = A + (size_t)(bm + lrow) * K + kq;
    const float* Wp = W + (size_t)(bn + lrow) * K + kq;

    // compute mapping: 16x16 thread grid, 8x8 micro-tile
    const int ty = tid >> 4;            // 0..15
    const int tx = tid & 15;            // 0..15

    float acc[8][8];
#pragma unroll
    for (int i = 0; i < 8; i++)
#pragma unroll
        for (int j = 0; j < 8; j++) acc[i][j] = 0.f;

    float4 a4 = *(const float4*)Ap;
    float4 w4 = *(const float4*)Wp;

    for (int k0 = 0; k0 < K; k0 += BK) {
        // scatter-transpose into smem
        As[kq + 0][lrow] = a4.x; As[kq + 1][lrow] = a4.y;
        As[kq + 2][lrow] = a4.z; As[kq + 3][lrow] = a4.w;
        Ws[kq + 0][lrow] = w4.x; Ws[kq + 1][lrow] = w4.y;
        Ws[kq + 2][lrow] = w4.z; Ws[kq + 3][lrow] = w4.w;
        __syncthreads();

        // prefetch next tile (hide global latency behind the 512 FFMAs below)
        if (k0 + BK < K) {
            a4 = *(const float4*)(Ap + k0 + BK);
            w4 = *(const float4*)(Wp + k0 + BK);
        }

#pragma unroll
        for (int kk = 0; kk < BK; kk++) {
            float4 a0 = *(const float4*)&As[kk][ty * 8];
            float4 a1 = *(const float4*)&As[kk][ty * 8 + 4];
            float4 w0 = *(const float4*)&Ws[kk][tx * 8];
            float4 w1 = *(const float4*)&Ws[kk][tx * 8 + 4];
            float ar[8] = {a0.x, a0.y, a0.z, a0.w, a1.x, a1.y, a1.z, a1.w};
            float wr[8] = {w0.x, w0.y, w0.z, w0.w, w1.x, w1.y, w1.z, w1.w};
#pragma unroll
            for (int i = 0; i < 8; i++)
#pragma unroll
                for (int j = 0; j < 8; j++)
                    acc[i][j] = fmaf(ar[i], wr[j], acc[i][j]);
        }
        __syncthreads();
    }

    // epilogue
    float bv[8];
    if (WITH_BIAS) {
        float4 b0 = *(const float4*)&bias[bn + tx * 8];
        float4 b1 = *(const float4*)&bias[bn + tx * 8 + 4];
        bv[0]=b0.x; bv[1]=b0.y; bv[2]=b0.z; bv[3]=b0.w;
        bv[4]=b1.x; bv[5]=b1.y; bv[6]=b1.z; bv[7]=b1.w;
    }
#pragma unroll
    for (int i = 0; i < 8; i++) {
        size_t row = (size_t)(bm + ty * 8 + i);
        float* crow = C + row * N + bn + tx * 8;
        float o[8];
#pragma unroll
        for (int j = 0; j < 8; j++) {
            float val = acc[i][j];
            if (WITH_BIAS) val += bv[j];
            if (ACT == 1)  val = tanhf(val);
            o[j] = val;
        }
        *(float4*)(crow)     = make_float4(o[0], o[1], o[2], o[3]);
        *(float4*)(crow + 4) = make_float4(o[4], o[5], o[6], o[7]);
    }
}

// ---------------------------------------------------------------------------
// Sampler: one warp per (b, q, h); lane = channel within the head (HD == 32).
// Computes softmax over the 16 logits (redundantly per lane — broadcast loads),
// forms clipped sampling locations from ref_points + tanh offsets, bilinear
// samples g_v, accumulates the weighted sum, writes g_samp[(b,q), h*32+lane].
// ---------------------------------------------------------------------------
__global__ void __launch_bounds__(256) sampler_kernel(
    const float* __restrict__ v,
    const float* __restrict__ off,
    const float* __restrict__ attn,
    const float* __restrict__ refp,
    float* __restrict__ outp)
{
    const int w    = blockIdx.x * 8 + (threadIdx.x >> 5);   // warp id = (b*Q+q)*H + h
    const int lane = threadIdx.x & 31;
    const int h    = w & 7;
    const size_t bq = (size_t)(w >> 3);                     // b*Q + q
    const int b    = w >> 16;                               // / (Q*H) = / 65536

    // ---- softmax over 16 logits (all lanes read the same addresses: broadcast)
    const float* al = attn + bq * 128 + h * 16;
    float wgt[16];
    float m = -1e30f;
#pragma unroll
    for (int i = 0; i < 16; i++) { wgt[i] = al[i]; m = fmaxf(m, wgt[i]); }
    float s = 0.f;
#pragma unroll
    for (int i = 0; i < 16; i++) { wgt[i] = __expf(wgt[i] - m); s += wgt[i]; }
    const float inv = 1.f / s;

    const float* ofb = off  + bq * 256 + h * 32;   // (l,p,c) -> l*8 + p*2 + c
    const float* rp  = refp + bq * 8;              // (l,c)   -> l*2 + c

    const int   Wls[4]    = {128, 64, 32, 16};
    const int   starts[4] = {0, 16384, 20480, 21504};
    const size_t vbase0 = (size_t)b * VLENv * Ee + h * HDd + lane;

    float acc = 0.f;
#pragma unroll
    for (int l = 0; l < 4; l++) {
        const int   Wl = Wls[l];
        const float rx = rp[l * 2 + 0];
        const float ry = rp[l * 2 + 1];
        const size_t vb = vbase0 + (size_t)starts[l] * Ee;
        const float scale = 0.5f * (float)(Wl - 1);
#pragma unroll
        for (int p = 0; p < 4; p++) {
            float x = fminf(fmaxf(rx + ofb[l * 8 + p * 2 + 0], -1.f), 1.f);
            float y = fminf(fmaxf(ry + ofb[l * 8 + p * 2 + 1], -1.f), 1.f);
            float fx = (x + 1.f) * scale;
            float fy = (y + 1.f) * scale;
            float x0f = floorf(fx), y0f = floorf(fy);
            float wx = fx - x0f,    wy = fy - y0f;
            int x0 = min(max((int)x0f, 0), Wl - 1);
            int x1 = min(x0 + 1, Wl - 1);
            int y0 = min(max((int)y0f, 0), Wl - 1);
            int y1 = min(y0 + 1, Wl - 1);

            const float v00 = v[vb + (size_t)(y0 * Wl + x0) * Ee];
            const float v01 = v[vb + (size_t)(y0 * Wl + x1) * Ee];
            const float v10 = v[vb + (size_t)(y1 * Wl + x0) * Ee];
            const float v11 = v[vb + (size_t)(y1 * Wl + x1) * Ee];

            float top = v00 * (1.f - wx) + v01 * wx;
            float bot = v10 * (1.f - wx) + v11 * wx;
            float bil = top * (1.f - wy) + bot * wy;

            acc += wgt[l * 4 + p] * inv * bil;
        }
    }
    outp[bq * 256 + h * HDd + lane] = acc;
}

// ---------------------------------------------------------------------------
// kernel_launch
// inputs (metadata order): 0 queries, 1 ref_points, 2 value, 3 spatial_shapes,
//                          4 V_W, 5 off_W, 6 off_b, 7 attn_W, 8 attn_b, 9 out_W
// output: float32 (B, Q, E)
// ---------------------------------------------------------------------------
extern "C" void kernel_launch(void* const* d_in, const int* in_sizes, int n_in,
                              void* d_out, int out_size)
{
    const float* queries = (const float*)d_in[0];
    const float* refp    = (const float*)d_in[1];
    const float* value   = (const float*)d_in[2];
    const float* V_W     = (const float*)d_in[4];
    const float* off_W   = (const float*)d_in[5];
    const float* off_b   = (const float*)d_in[6];
    const float* attn_W  = (const float*)d_in[7];
    const float* attn_b  = (const float*)d_in[8];
    const float* out_W   = (const float*)d_in[9];
    float* out = (float*)d_out;

    float *pv, *poff, *pattn, *psamp;
    cudaGetSymbolAddress((void**)&pv,    g_v);
    cudaGetSymbolAddress((void**)&poff,  g_off);
    cudaGetSymbolAddress((void**)&pattn, g_attn);
    cudaGetSymbolAddress((void**)&psamp, g_samp);

    const int MV = Bb * VLENv;   // 87040  (% 128 == 0)
    const int MQ = Bb * Qq;      // 32768  (% 128 == 0)

    dim3 blk(256);

    // 1) v = value @ V_W^T
    sgemm_tn<0, 0><<<dim3(Ee / 128, MV / 128), blk>>>(value, V_W, nullptr, pv, MV, Ee, Ee);
    // 2) off = tanh(queries @ off_W^T + off_b)
    sgemm_tn<1, 1><<<dim3(Ee / 128, MQ / 128), blk>>>(queries, off_W, off_b, poff, MQ, Ee, Ee);
    // 3) attn logits = queries @ attn_W^T + attn_b
    sgemm_tn<0, 1><<<dim3(128 / 128, MQ / 128), blk>>>(queries, attn_W, attn_b, pattn, MQ, 128, Ee);
    // 4) softmax + bilinear sampling + weighted sum
    sampler_kernel<<<(Bb * Qq * Hh) / 8, 256>>>(pv, poff, pattn, refp, psamp);
    // 5) out = samp @ out_W^T
    sgemm_tn<0, 0><<<dim3(Ee / 128, MQ / 128), blk>>>(psamp, out_W, nullptr, out, MQ, Ee, Ee);
}

// round 5
// speedup vs baseline: 1.7098x; 1.7098x over previous
#include <cuda_runtime.h>
#include <math.h>

// ---------------- problem constants ----------------
#define Bb   4
#define Qq   8192
#define Ee   256
#define Hh   8
#define Ll   4
#define Pp   4
#define HDd  32
#define VLENv 21760   // 128*128 + 64*64 + 32*32 + 16*16

// ---------------- scratch (device globals; no allocation allowed) ----------------
__device__ float g_v   [(size_t)Bb * VLENv * Ee];   // value @ V_W^T        (~89 MB)
__device__ float g_off [(size_t)Bb * Qq   * Ee];    // tanh offsets         (~34 MB)
__device__ float g_attn[(size_t)Bb * Qq   * 128];   // attention logits     (~17 MB)
__device__ float g_samp[(size_t)Bb * Qq   * Ee];    // sampled output       (~34 MB)

// ---------------------------------------------------------------------------
// Generic SGEMM:  C[M,N] = act( A[M,K] @ W[N,K]^T + bias )
// Double-buffered smem: one __syncthreads per BK-tile, compute overlaps refill.
// Tile: BM=BN=128, BK=8, 256 threads, 8x8 outputs/thread.
// Requires: M%128==0, N%128==0, K%8==0, 16B-aligned pointers. (All true here.)
// ---------------------------------------------------------------------------
template<int ACT, int WITH_BIAS>
__global__ void __launch_bounds__(256) sgemm_tn(
    const float* __restrict__ A,
    const float* __restrict__ W,
    const float* __restrict__ bias,
    float* __restrict__ C,
    int M, int N, int K)
{
    constexpr int BM = 128, BN = 128, BK = 8;
    __shared__ __align__(16) float As[2][BK][BM + 4];
    __shared__ __align__(16) float Ws[2][BK][BN + 4];

    const int tid = threadIdx.x;
    const int bm  = blockIdx.y * BM;
    const int bn  = blockIdx.x * BN;

    // global->smem load mapping: each thread loads one float4 from A and one from W
    const int lrow = tid >> 1;          // 0..127
    const int kq   = (tid & 1) * 4;     // 0 or 4

    const float* Ap = A + (size_t)(bm + lrow) * K + kq;
    const float* Wp = W + (size_t)(bn + lrow) * K + kq;

    // compute mapping: 16x16 thread grid, 8x8 micro-tile
    const int ty = tid >> 4;            // 0..15
    const int tx = tid & 15;            // 0..15

    float acc[8][8];
#pragma unroll
    for (int i = 0; i < 8; i++)
#pragma unroll
        for (int j = 0; j < 8; j++) acc[i][j] = 0.f;

    // preload tile 0
    float4 a4 = *(const float4*)Ap;
    float4 w4 = *(const float4*)Wp;
    int buf = 0;
    As[0][kq + 0][lrow] = a4.x; As[0][kq + 1][lrow] = a4.y;
    As[0][kq + 2][lrow] = a4.z; As[0][kq + 3][lrow] = a4.w;
    Ws[0][kq + 0][lrow] = w4.x; Ws[0][kq + 1][lrow] = w4.y;
    Ws[0][kq + 2][lrow] = w4.z; Ws[0][kq + 3][lrow] = w4.w;
    __syncthreads();

    for (int k0 = 0; k0 < K; k0 += BK) {
        const bool has_next = (k0 + BK < K);
        if (has_next) {
            a4 = *(const float4*)(Ap + k0 + BK);
            w4 = *(const float4*)(Wp + k0 + BK);
        }

#pragma unroll
        for (int kk = 0; kk < BK; kk++) {
            float4 a0 = *(const float4*)&As[buf][kk][ty * 8];
            float4 a1 = *(const float4*)&As[buf][kk][ty * 8 + 4];
            float4 w0 = *(const float4*)&Ws[buf][kk][tx * 8];
            float4 w1 = *(const float4*)&Ws[buf][kk][tx * 8 + 4];
            float ar[8] = {a0.x, a0.y, a0.z, a0.w, a1.x, a1.y, a1.z, a1.w};
            float wr[8] = {w0.x, w0.y, w0.z, w0.w, w1.x, w1.y, w1.z, w1.w};
#pragma unroll
            for (int i = 0; i < 8; i++)
#pragma unroll
                for (int j = 0; j < 8; j++)
                    acc[i][j] = fmaf(ar[i], wr[j], acc[i][j]);
        }

        if (has_next) {
            const int nb = buf ^ 1;
            As[nb][kq + 0][lrow] = a4.x; As[nb][kq + 1][lrow] = a4.y;
            As[nb][kq + 2][lrow] = a4.z; As[nb][kq + 3][lrow] = a4.w;
            Ws[nb][kq + 0][lrow] = w4.x; Ws[nb][kq + 1][lrow] = w4.y;
            Ws[nb][kq + 2][lrow] = w4.z; Ws[nb][kq + 3][lrow] = w4.w;
            __syncthreads();
            buf = nb;
        }
    }

    // epilogue
    float bv[8];
    if (WITH_BIAS) {
        float4 b0 = *(const float4*)&bias[bn + tx * 8];
        float4 b1 = *(const float4*)&bias[bn + tx * 8 + 4];
        bv[0]=b0.x; bv[1]=b0.y; bv[2]=b0.z; bv[3]=b0.w;
        bv[4]=b1.x; bv[5]=b1.y; bv[6]=b1.z; bv[7]=b1.w;
    }
#pragma unroll
    for (int i = 0; i < 8; i++) {
        size_t row = (size_t)(bm + ty * 8 + i);
        float* crow = C + row * N + bn + tx * 8;
        float o[8];
#pragma unroll
        for (int j = 0; j < 8; j++) {
            float val = acc[i][j];
            if (WITH_BIAS) val += bv[j];
            if (ACT == 1)  val = tanhf(val);
            o[j] = val;
        }
        *(float4*)(crow)     = make_float4(o[0], o[1], o[2], o[3]);
        *(float4*)(crow + 4) = make_float4(o[4], o[5], o[6], o[7]);
    }
}

// ---------------------------------------------------------------------------
// Sampler v2: one warp per (b, q, h).
// Lane l -> (tap r = l>>1, channel-half j = l&1).
//   * softmax weight, coordinates, integer indexing computed ONCE per tap
//     (was: redundantly by all 32 lanes)
//   * each lane loads its tap's 4 bilinear corners as 4x float4 (16 channels)
//     -> LDG.128 instead of LDG.32 (4x fewer load instructions, same bytes)
//   * 16-float per-lane contribution reduced across the 16 taps with a
//     4-step shfl butterfly (xor 2,4,8,16; j-duplicates make it exact)
//   * lanes with r==0 (lane 0: j=0 half, lane 1: j=1 half) store 4x float4
// ---------------------------------------------------------------------------
__global__ void __launch_bounds__(256) sampler_kernel(
    const float* __restrict__ v,
    const float* __restrict__ off,
    const float* __restrict__ attn,
    const float* __restrict__ refp,
    float* __restrict__ outp)
{
    const int wid  = blockIdx.x * 8 + (threadIdx.x >> 5);   // (b*Q+q)*H + h
    const int lane = threadIdx.x & 31;
    const int h    = wid & 7;
    const size_t bq = (size_t)(wid >> 3);                   // b*Q + q
    const int b    = wid >> 16;                             // / (Q*H) = / 65536

    const int r   = lane >> 1;          // tap 0..15  (= l*4 + p)
    const int j   = lane & 1;           // channel half (16 floats each)
    const int lev = r >> 2;             // level 0..3
    const int Wl  = 128 >> lev;         // 128,64,32,16
    const int start = (65536 - ((Wl * Wl) << 2)) / 3;  // 0,16384,20480,21504

    // ---- softmax over the 16 taps (value duplicated across j; butterfly over
    //      xor {2,4,8,16} reduces across all 16 taps, leaves result in all lanes)
    float logit = attn[bq * 128 + h * 16 + r];
    float m = logit;
#pragma unroll
    for (int s = 2; s < 32; s <<= 1)
        m = fmaxf(m, __shfl_xor_sync(0xffffffffu, m, s));
    float e = __expf(logit - m);
    float ssum = e;
#pragma unroll
    for (int s = 2; s < 32; s <<= 1)
        ssum += __shfl_xor_sync(0xffffffffu, ssum, s);
    const float wgt = e / ssum;

    // ---- sampling location for tap r
    const float rx = refp[bq * 8 + lev * 2 + 0];
    const float ry = refp[bq * 8 + lev * 2 + 1];
    const float ox = off[bq * 256 + h * 32 + r * 2 + 0];
    const float oy = off[bq * 256 + h * 32 + r * 2 + 1];
    const float x = fminf(fmaxf(rx + ox, -1.f), 1.f);
    const float y = fminf(fmaxf(ry + oy, -1.f), 1.f);
    const float scale = 0.5f * (float)(Wl - 1);
    const float fx = (x + 1.f) * scale;
    const float fy = (y + 1.f) * scale;
    const float x0f = floorf(fx), y0f = floorf(fy);
    const float wx = fx - x0f,    wy = fy - y0f;
    int x0 = min(max((int)x0f, 0), Wl - 1);
    int x1 = min(x0 + 1, Wl - 1);
    int y0 = min(max((int)y0f, 0), Wl - 1);
    int y1 = min(y0 + 1, Wl - 1);

    // corner weights, pre-multiplied by the attention weight
    const float w00 = wgt * (1.f - wx) * (1.f - wy);
    const float w01 = wgt * wx * (1.f - wy);
    const float w10 = wgt * (1.f - wx) * wy;
    const float w11 = wgt * wx * wy;

    // ---- vectorized corner loads + bilinear combine (16 channels per lane)
    const float* base = v + ((size_t)b * VLENv + start) * Ee + h * HDd + j * 16;
    const float4* p00 = (const float4*)(base + (size_t)(y0 * Wl + x0) * Ee);
    const float4* p01 = (const float4*)(base + (size_t)(y0 * Wl + x1) * Ee);
    const float4* p10 = (const float4*)(base + (size_t)(y1 * Wl + x0) * Ee);
    const float4* p11 = (const float4*)(base + (size_t)(y1 * Wl + x1) * Ee);

    float acc[16];
#pragma unroll
    for (int k = 0; k < 4; k++) {
        const float4 c00 = p00[k];
        const float4 c01 = p01[k];
        const float4 c10 = p10[k];
        const float4 c11 = p11[k];
        acc[4*k+0] = w00*c00.x + w01*c01.x + w10*c10.x + w11*c11.x;
        acc[4*k+1] = w00*c00.y + w01*c01.y + w10*c10.y + w11*c11.y;
        acc[4*k+2] = w00*c00.z + w01*c01.z + w10*c10.z + w11*c11.z;
        acc[4*k+3] = w00*c00.w + w01*c01.w + w10*c10.w + w11*c11.w;
    }

    // ---- reduce across the 16 taps (same-j lanes)
#pragma unroll
    for (int s = 2; s < 32; s <<= 1) {
#pragma unroll
        for (int k = 0; k < 16; k++)
            acc[k] += __shfl_xor_sync(0xffffffffu, acc[k], s);
    }

    // ---- store: lane 0 writes channels [0,16), lane 1 writes [16,32)
    if (r == 0) {
        float4* o = (float4*)(outp + bq * 256 + h * HDd + j * 16);
        o[0] = make_float4(acc[0],  acc[1],  acc[2],  acc[3]);
        o[1] = make_float4(acc[4],  acc[5],  acc[6],  acc[7]);
        o[2] = make_float4(acc[8],  acc[9],  acc[10], acc[11]);
        o[3] = make_float4(acc[12], acc[13], acc[14], acc[15]);
    }
}

// ---------------------------------------------------------------------------
// kernel_launch
// inputs (metadata order): 0 queries, 1 ref_points, 2 value, 3 spatial_shapes,
//                          4 V_W, 5 off_W, 6 off_b, 7 attn_W, 8 attn_b, 9 out_W
// output: float32 (B, Q, E)
// ---------------------------------------------------------------------------
extern "C" void kernel_launch(void* const* d_in, const int* in_sizes, int n_in,
                              void* d_out, int out_size)
{
    const float* queries = (const float*)d_in[0];
    const float* refp    = (const float*)d_in[1];
    const float* value   = (const float*)d_in[2];
    const float* V_W     = (const float*)d_in[4];
    const float* off_W   = (const float*)d_in[5];
    const float* off_b   = (const float*)d_in[6];
    const float* attn_W  = (const float*)d_in[7];
    const float* attn_b  = (const float*)d_in[8];
    const float* out_W   = (const float*)d_in[9];
    float* out = (float*)d_out;

    float *pv, *poff, *pattn, *psamp;
    cudaGetSymbolAddress((void**)&pv,    g_v);
    cudaGetSymbolAddress((void**)&poff,  g_off);
    cudaGetSymbolAddress((void**)&pattn, g_attn);
    cudaGetSymbolAddress((void**)&psamp, g_samp);

    const int MV = Bb * VLENv;   // 87040  (% 128 == 0)
    const int MQ = Bb * Qq;      // 32768  (% 128 == 0)

    dim3 blk(256);

    // 1) v = value @ V_W^T
    sgemm_tn<0, 0><<<dim3(Ee / 128, MV / 128), blk>>>(value, V_W, nullptr, pv, MV, Ee, Ee);
    // 2) off = tanh(queries @ off_W^T + off_b)
    sgemm_tn<1, 1><<<dim3(Ee / 128, MQ / 128), blk>>>(queries, off_W, off_b, poff, MQ, Ee, Ee);
    // 3) attn logits = queries @ attn_W^T + attn_b
    sgemm_tn<0, 1><<<dim3(128 / 128, MQ / 128), blk>>>(queries, attn_W, attn_b, pattn, MQ, 128, Ee);
    // 4) softmax + bilinear sampling + weighted sum
    sampler_kernel<<<(Bb * Qq * Hh) / 8, 256>>>(pv, poff, pattn, refp, psamp);
    // 5) out = samp @ out_W^T
    sgemm_tn<0, 0><<<dim3(Ee / 128, MQ / 128), blk>>>(psamp, out_W, nullptr, out, MQ, Ee, Ee);
}